// round 6
// baseline (speedup 1.0000x reference)
#include <cuda_runtime.h>
#include <math.h>

#define BB 8192
#define DD 384
#define EE 1024
#define RR 8
#define HH 64
#define DPAD 18
#define GRID_UV 400        // 128 ev tiles + <=264 xu tiles (64 rows each)
#define GRID_MAIN 640      // >= sum_p ceil(pcnt[p]/16) <= 575
#define DC 64              // d-chunk for k_uv
#define XSTR 68            // row stride of shared staging buffer

typedef unsigned long long ull;

// ---------------- device scratch ----------------
__device__ float g_evt[RR * HH * EE];   // ev transposed [r][h][e]  (2 MB)
__device__ float g_xu[BB * 2 * HH];     // normalized xu per assignment code (4 MB)
__device__ float g_gw[BB * 2];
__device__ int   g_cnt[RR];
__device__ int   g_list[RR * BB];       // router-grouped codes (b*2+k)
__device__ int   g_pcnt[64];
__device__ int   g_plist[64 * BB];      // pair-grouped token ids
__device__ int   g_uvtile[GRID_UV];
__device__ int   g_ptile[GRID_MAIN];
__device__ float g_sumP[RR];
__device__ float g_sumM[RR];

// ---------------- f32x2 helpers ----------------
__device__ __forceinline__ ull pk2(float a, float b) {
    ull r; asm("mov.b64 %0, {%1,%2};" : "=l"(r) : "f"(a), "f"(b)); return r;
}
__device__ __forceinline__ void upk2(ull v, float& lo, float& hi) {
    asm("mov.b64 {%0,%1}, %2;" : "=f"(lo), "=f"(hi) : "l"(v));
}
__device__ __forceinline__ ull fma2(ull a, ull b, ull c) {
    ull d; asm("fma.rn.f32x2 %0, %1, %2, %3;" : "=l"(d) : "l"(a), "l"(b), "l"(c)); return d;
}

// ---------------- kernel 0: init ----------------
__global__ void k_init() {
    int t = threadIdx.x;
    if (t < RR) { g_cnt[t] = 0; g_sumP[t] = 0.f; g_sumM[t] = 0.f; }
    if (t < 64) g_pcnt[t] = 0;
}

// ---------------- kernel 1: gate ----------------
__global__ void __launch_bounds__(256) k_gate(const float* __restrict__ x,
                                              const float* __restrict__ gw,
                                              const float* __restrict__ gb) {
    __shared__ float sP[RR], sM[RR];
    int tid = threadIdx.x;
    if (tid < RR) { sP[tid] = 0.f; sM[tid] = 0.f; }
    __syncthreads();

    int warp = tid >> 5, lane = tid & 31;
    int b = blockIdx.x * 8 + warp;

    float acc[RR];
#pragma unroll
    for (int r = 0; r < RR; r++) acc[r] = 0.f;
    const float* xr = x + b * DD;
    for (int d = lane; d < DD; d += 32) {
        float xv = xr[d];
        const float4* g4 = (const float4*)(gw + d * RR);
        float4 a = g4[0], c = g4[1];
        acc[0] += xv * a.x; acc[1] += xv * a.y; acc[2] += xv * a.z; acc[3] += xv * a.w;
        acc[4] += xv * c.x; acc[5] += xv * c.y; acc[6] += xv * c.z; acc[7] += xv * c.w;
    }
#pragma unroll
    for (int r = 0; r < RR; r++)
#pragma unroll
        for (int o = 16; o; o >>= 1) acc[r] += __shfl_xor_sync(0xffffffffu, acc[r], o);

    if (lane == 0) {
        float lg[RR];
#pragma unroll
        for (int r = 0; r < RR; r++) lg[r] = acc[r] + gb[r];
        int i0 = 0; float v0 = lg[0];
#pragma unroll
        for (int r = 1; r < RR; r++) if (lg[r] > v0) { v0 = lg[r]; i0 = r; }
        int i1 = -1; float v1 = -3.0e38f;
#pragma unroll
        for (int r = 0; r < RR; r++) if (r != i0 && lg[r] > v1) { v1 = lg[r]; i1 = r; }

        float s = 0.f, pr[RR];
#pragma unroll
        for (int r = 0; r < RR; r++) { pr[r] = expf(lg[r] - v0); s += pr[r]; }
        float inv = 1.f / s;
#pragma unroll
        for (int r = 0; r < RR; r++) atomicAdd(&sP[r], pr[r] * inv);
        atomicAdd(&sM[i0], 1.f);
        atomicAdd(&sM[i1], 1.f);

        float e1 = expf(v1 - v0);
        float den = 1.f / (1.f + e1);
        g_gw[b * 2 + 0] = den;
        g_gw[b * 2 + 1] = e1 * den;

        int p0 = atomicAdd(&g_cnt[i0], 1); g_list[i0 * BB + p0] = b * 2 + 0;
        int p1 = atomicAdd(&g_cnt[i1], 1); g_list[i1 * BB + p1] = b * 2 + 1;

        int pid = i0 * 8 + i1;
        int pp = atomicAdd(&g_pcnt[pid], 1); g_plist[pid * BB + pp] = b;
    }
    __syncthreads();
    if (tid < RR) { atomicAdd(&g_sumP[tid], sP[tid]); atomicAdd(&g_sumM[tid], sM[tid]); }
}

// ---------------- kernel 2: scheduler ----------------
__global__ void k_sched() {
    int tid = threadIdx.x;
    for (int i = tid; i < GRID_UV; i += 256) g_uvtile[i] = -1;
    for (int i = tid; i < GRID_MAIN; i += 256) g_ptile[i] = -1;
    __shared__ int roff[RR], poff[64];
    if (tid == 0) {
        int o = 128;   // xu tiles start after the 128 static ev tiles
        for (int r = 0; r < RR; r++) { roff[r] = o; o += (g_cnt[r] + 63) >> 6; }
        o = 0;
        for (int p = 0; p < 64; p++) { poff[p] = o; o += (g_pcnt[p] + 15) >> 4; }
    }
    __syncthreads();
    if (tid < 128) g_uvtile[tid] = ((tid >> 4) << 24) | (tid & 15);   // type 0 (ev)
    if (tid >= 128 && tid < 128 + RR) {
        int r = tid - 128;
        int n = (g_cnt[r] + 63) >> 6;
        for (int i = 0; i < n; i++) g_uvtile[roff[r] + i] = (1 << 28) | (r << 24) | i;
    }
    if (tid >= 192 && tid < 256) {
        int p = tid - 192;
        int n = (g_pcnt[p] + 15) >> 4;
        for (int i = 0; i < n; i++) g_ptile[poff[p] + i] = (p << 16) | i;
    }
}

// ---------------- kernel 3: unified ev/xu GEMM (256 thr, 64x64 tile, 4 rows/lane) ----------------
__global__ void __launch_bounds__(256) k_uv(const float* __restrict__ x,
                                            const float* __restrict__ re,
                                            const float* __restrict__ Uw,
                                            const float* __restrict__ Ub,
                                            const float* __restrict__ Vw,
                                            const float* __restrict__ Vb) {
    __shared__ float buf[DC * XSTR];  // xT[d][row] during compute; outT[h][row] in epilogue
    __shared__ int   s_code[64];

    int info = g_uvtile[blockIdx.x];
    if (info < 0) return;
    int type = (info >> 28) & 1;
    int r    = (info >> 24) & 15;
    int tile = info & 0xffffff;
    int tid = threadIdx.x;

    const float* W    = (type == 0) ? (Vw + r * DD * HH) : (Uw + r * DD * HH);
    const float* bias = (type == 0) ? (Vb + r * HH)      : (Ub + r * HH);

    if (tid < 64) {
        if (type == 0) s_code[tid] = tile * 64 + tid;
        else {
            int cnt = g_cnt[r], base = tile * 64;
            s_code[tid] = (base + tid < cnt) ? g_list[r * BB + base + tid] : -1;
        }
    }
    __syncthreads();

    int w = tid >> 5, l = tid & 31;
    int hq = l & 15, rg = l >> 4;
    int h0 = hq * 4;
    int wrow = w * 8 + rg * 4;       // 4 rows (2 f32x2 pairs) per lane

    // staging: thread t stages row (t&63), d-quarter (t>>6): 16 floats
    int srow = tid & 63, sq = tid >> 6;
    const float* src;
    {
        int c = s_code[srow];
        if (type == 0) src = re + (long)c * DD;
        else           src = (c >= 0) ? (x + (long)(c >> 1) * DD) : (const float*)0;
    }

    ull acc[2][4];                   // [row-pair][h-elem]
#pragma unroll
    for (int a = 0; a < 2; a++)
#pragma unroll
        for (int b = 0; b < 4; b++) acc[a][b] = 0ULL;

    for (int dc = 0; dc < DD; dc += DC) {
        if (src) {
#pragma unroll
            for (int i = 0; i < 4; i++) {
                int d = sq * 16 + i * 4;
                float4 v = *(const float4*)(src + dc + d);
                buf[(d + 0) * XSTR + srow] = v.x; buf[(d + 1) * XSTR + srow] = v.y;
                buf[(d + 2) * XSTR + srow] = v.z; buf[(d + 3) * XSTR + srow] = v.w;
            }
        } else {
#pragma unroll
            for (int i = 0; i < 4; i++) {
                int d = sq * 16 + i * 4;
                buf[(d + 0) * XSTR + srow] = 0.f; buf[(d + 1) * XSTR + srow] = 0.f;
                buf[(d + 2) * XSTR + srow] = 0.f; buf[(d + 3) * XSTR + srow] = 0.f;
            }
        }
        __syncthreads();

#pragma unroll 4
        for (int d = 0; d < DC; d++) {
            float4 wv = *(const float4*)(W + (dc + d) * HH + h0);   // per-lane, L1-resident
            ull b0 = pk2(wv.x, wv.x), b1 = pk2(wv.y, wv.y);
            ull b2 = pk2(wv.z, wv.z), b3 = pk2(wv.w, wv.w);
            const ull* xp = (const ull*)&buf[d * XSTR + wrow];      // broadcast row-pairs
            ull x0 = xp[0], x1 = xp[1];
            acc[0][0] = fma2(x0, b0, acc[0][0]); acc[0][1] = fma2(x0, b1, acc[0][1]);
            acc[0][2] = fma2(x0, b2, acc[0][2]); acc[0][3] = fma2(x0, b3, acc[0][3]);
            acc[1][0] = fma2(x1, b0, acc[1][0]); acc[1][1] = fma2(x1, b1, acc[1][1]);
            acc[1][2] = fma2(x1, b2, acc[1][2]); acc[1][3] = fma2(x1, b3, acc[1][3]);
        }
        __syncthreads();
    }

    // epilogue: bias, per-row l2 norm (reduce over the 16 same-rg lanes), store
    float bl[4];
#pragma unroll
    for (int k = 0; k < 4; k++) bl[k] = bias[h0 + k];

#pragma unroll
    for (int rp = 0; rp < 2; rp++) {
        float vlo[4], vhi[4];
        float slo = 0.f, shi = 0.f;
#pragma unroll
        for (int k = 0; k < 4; k++) {
            float lo, hi;
            upk2(acc[rp][k], lo, hi);
            lo += bl[k]; hi += bl[k];
            vlo[k] = lo; vhi[k] = hi;
            slo += lo * lo; shi += hi * hi;
        }
#pragma unroll
        for (int o = 1; o <= 8; o <<= 1) {
            slo += __shfl_xor_sync(0xffffffffu, slo, o);
            shi += __shfl_xor_sync(0xffffffffu, shi, o);
        }
        float rnlo = 1.f / fmaxf(sqrtf(slo), 1e-12f);
        float rnhi = 1.f / fmaxf(sqrtf(shi), 1e-12f);

        int row0 = wrow + 2 * rp;
        if (type == 1) {
            int c0 = s_code[row0], c1 = s_code[row0 + 1];
            if (c0 >= 0) {
                float4 o0 = make_float4(vlo[0] * rnlo, vlo[1] * rnlo, vlo[2] * rnlo, vlo[3] * rnlo);
                *(float4*)(g_xu + c0 * HH + h0) = o0;
            }
            if (c1 >= 0) {
                float4 o1 = make_float4(vhi[0] * rnhi, vhi[1] * rnhi, vhi[2] * rnhi, vhi[3] * rnhi);
                *(float4*)(g_xu + c1 * HH + h0) = o1;
            }
        } else {
#pragma unroll
            for (int k = 0; k < 4; k++) {
                buf[(h0 + k) * XSTR + row0]     = vlo[k] * rnlo;   // outT[h][row]
                buf[(h0 + k) * XSTR + row0 + 1] = vhi[k] * rnhi;
            }
        }
    }
    if (type == 0) {
        __syncthreads();
        int h = tid >> 2, q = tid & 3;
        int ebase = tile * 64;
        float* dst = g_evt + (r * HH + h) * EE + ebase + q * 16;
        const float* s = &buf[h * XSTR + q * 16];
#pragma unroll
        for (int i = 0; i < 4; i++) {
            float4 o = make_float4(s[i * 4 + 0], s[i * 4 + 1], s[i * 4 + 2], s[i * 4 + 3]);
            *(float4*)(dst + i * 4) = o;
        }
    }
}

// ---------------- kernel 4: pair-grouped scores + softmax + combine + sample ----------------
__global__ void __launch_bounds__(256, 2) k_main(const float* __restrict__ rnd,
                                                 float* __restrict__ out) {
    extern __shared__ float dyn[];
    float* p_s = dyn;                            // [16][1024]  64KB
    float* xu_s = dyn + 16 * EE;                 // [2][64][18] 9.2KB
    __shared__ int   s_b[16];
    __shared__ float s_w[2][16];
    __shared__ float red[8][16];
    __shared__ float rowstat[16];
    __shared__ float s_scale[16];

    int info = g_ptile[blockIdx.x];
    if (info < 0) return;
    int pid = info >> 16, base = (info & 0xffff) * 16;
    int r0 = pid >> 3, r1 = pid & 7;
    int cnt = g_pcnt[pid];
    int nt = min(16, cnt - base);
    int tid = threadIdx.x;

    if (tid < 16) {
        int b = (tid < nt) ? g_plist[pid * BB + base + tid] : -1;
        s_b[tid] = b;
        s_w[0][tid] = (b >= 0) ? g_gw[b * 2 + 0] : 0.f;
        s_w[1][tid] = (b >= 0) ? g_gw[b * 2 + 1] : 0.f;
    }
    __syncthreads();
    {   // load xu for both slots, transposed into [h][t]
        int s = tid >> 7, c = (tid >> 3) & 15, h0 = (tid & 7) * 8;
        int b = s_b[c];
        float* dst = xu_s + s * (HH * DPAD);
        if (b >= 0) {
            const float4* src = (const float4*)(g_xu + (b * 2 + s) * HH + h0);
            float4 v0 = src[0], v1 = src[1];
            dst[(h0 + 0) * DPAD + c] = v0.x; dst[(h0 + 1) * DPAD + c] = v0.y;
            dst[(h0 + 2) * DPAD + c] = v0.z; dst[(h0 + 3) * DPAD + c] = v0.w;
            dst[(h0 + 4) * DPAD + c] = v1.x; dst[(h0 + 5) * DPAD + c] = v1.y;
            dst[(h0 + 6) * DPAD + c] = v1.z; dst[(h0 + 7) * DPAD + c] = v1.w;
        } else {
#pragma unroll
            for (int j = 0; j < 8; j++) dst[(h0 + j) * DPAD + c] = 0.f;
        }
    }
    __syncthreads();

    int e0 = tid * 4;
    int lane = tid & 31, w = tid >> 5;

    for (int ph = 0; ph < 2; ph++) {
        int r = ph ? r1 : r0;
        ull acc2[8][4];
#pragma unroll
        for (int tp = 0; tp < 8; tp++)
#pragma unroll
            for (int j = 0; j < 4; j++) acc2[tp][j] = 0ULL;

        const float* evr = g_evt + r * HH * EE;
        const float* xub = xu_s + ph * (HH * DPAD);
#pragma unroll 4
        for (int h = 0; h < HH; h++) {
            float4 ev4 = *(const float4*)(evr + h * EE + e0);
            ull bx = pk2(ev4.x, ev4.x);
            ull by = pk2(ev4.y, ev4.y);
            ull bz = pk2(ev4.z, ev4.z);
            ull bw = pk2(ev4.w, ev4.w);
            const ull* xp = (const ull*)(xub + h * DPAD);
#pragma unroll
            for (int tp = 0; tp < 8; tp++) {
                ull xs2 = xp[tp];
                acc2[tp][0] = fma2(xs2, bx, acc2[tp][0]);
                acc2[tp][1] = fma2(xs2, by, acc2[tp][1]);
                acc2[tp][2] = fma2(xs2, bz, acc2[tp][2]);
                acc2[tp][3] = fma2(xs2, bw, acc2[tp][3]);
            }
        }

        // row max
        {
            float lmax[16];
#pragma unroll
            for (int t = 0; t < 16; t++) lmax[t] = -3.0e38f;
#pragma unroll
            for (int tp = 0; tp < 8; tp++)
#pragma unroll
                for (int j = 0; j < 4; j++) {
                    float lo, hi;
                    upk2(acc2[tp][j], lo, hi);
                    lmax[2 * tp]     = fmaxf(lmax[2 * tp], lo);
                    lmax[2 * tp + 1] = fmaxf(lmax[2 * tp + 1], hi);
                }
#pragma unroll
            for (int t = 0; t < 16; t++)
#pragma unroll
                for (int o = 16; o; o >>= 1)
                    lmax[t] = fmaxf(lmax[t], __shfl_xor_sync(0xffffffffu, lmax[t], o));
            if (lane == 0)
#pragma unroll
                for (int t = 0; t < 16; t++) red[w][t] = lmax[t];
        }
        __syncthreads();
        if (tid < 16) {
            float m = red[0][tid];
#pragma unroll
            for (int ww = 1; ww < 8; ww++) m = fmaxf(m, red[ww][tid]);
            rowstat[tid] = m;
        }
        __syncthreads();

        // exp + row sum
        {
            float lsum[16];
#pragma unroll
            for (int t = 0; t < 16; t++) lsum[t] = 0.f;
#pragma unroll
            for (int tp = 0; tp < 8; tp++) {
                float m0 = rowstat[2 * tp], m1 = rowstat[2 * tp + 1];
#pragma unroll
                for (int j = 0; j < 4; j++) {
                    float lo, hi;
                    upk2(acc2[tp][j], lo, hi);
                    float elo = __expf(lo - m0);
                    float ehi = __expf(hi - m1);
                    lsum[2 * tp]     += elo;
                    lsum[2 * tp + 1] += ehi;
                    acc2[tp][j] = pk2(elo, ehi);
                }
            }
#pragma unroll
            for (int t = 0; t < 16; t++)
#pragma unroll
                for (int o = 16; o; o >>= 1)
                    lsum[t] += __shfl_xor_sync(0xffffffffu, lsum[t], o);
            if (lane == 0)
#pragma unroll
                for (int t = 0; t < 16; t++) red[w][t] = lsum[t];
        }
        __syncthreads();
        if (tid < 16) {
            float s = 0.f;
#pragma unroll
            for (int ww = 0; ww < 8; ww++) s += red[ww][tid];
            s_scale[tid] = s_w[ph][tid] / s;
        }
        __syncthreads();

        // store (ph 0) or combine (ph 1)
#pragma unroll
        for (int tp = 0; tp < 8; tp++) {
            int t0 = 2 * tp, t1 = 2 * tp + 1;
            float sc0 = s_scale[t0], sc1 = s_scale[t1];
            float4 olo, ohi;
            float lo, hi;
            upk2(acc2[tp][0], lo, hi); olo.x = lo * sc0; ohi.x = hi * sc1;
            upk2(acc2[tp][1], lo, hi); olo.y = lo * sc0; ohi.y = hi * sc1;
            upk2(acc2[tp][2], lo, hi); olo.z = lo * sc0; ohi.z = hi * sc1;
            upk2(acc2[tp][3], lo, hi); olo.w = lo * sc0; ohi.w = hi * sc1;
            float4* d0 = (float4*)(p_s + t0 * EE + e0);
            float4* d1 = (float4*)(p_s + t1 * EE + e0);
            if (ph == 0) {
                *d0 = olo; *d1 = ohi;
            } else {
                float4 a = *d0, c = *d1;
                a.x += olo.x; a.y += olo.y; a.z += olo.z; a.w += olo.w;
                c.x += ohi.x; c.y += ohi.y; c.z += ohi.z; c.w += ohi.w;
                *d0 = a; *d1 = c;
            }
        }
        __syncthreads();
    }

    // sampling: warp w handles tokens 2w, 2w+1
#pragma unroll
    for (int k = 0; k < 2; k++) {
        int t = w * 2 + k;
        int b = s_b[t];
        if (b < 0) continue;
        float rv = rnd[b];
        int ebase2 = lane * 32;
        float v[32];
        const float4* pr = (const float4*)(p_s + t * EE + ebase2);
#pragma unroll
        for (int q = 0; q < 8; q++) {
            float4 f = pr[q];
            v[q * 4 + 0] = f.x; v[q * 4 + 1] = f.y; v[q * 4 + 2] = f.z; v[q * 4 + 3] = f.w;
        }
        float lsum = 0.f;
#pragma unroll
        for (int i = 0; i < 32; i++) lsum += v[i];
        float sc = lsum;
#pragma unroll
        for (int o = 1; o < 32; o <<= 1) {
            float u = __shfl_up_sync(0xffffffffu, sc, o);
            if (lane >= o) sc += u;
        }
        float run = sc - lsum;   // exclusive prefix
        int cand = 0x7fffffff;
        float pv = 0.f;
#pragma unroll
        for (int i = 0; i < 32; i++) {
            run += v[i];
            if (cand == 0x7fffffff && run > rv) { cand = ebase2 + i; pv = v[i]; }
        }
        unsigned mask = __ballot_sync(0xffffffffu, cand != 0x7fffffff);
        if (mask == 0) {
            if (lane == 0) { out[b] = 0.f; out[BB + b] = logf(v[0]); }
        } else {
            int firstlane = __ffs(mask) - 1;
            if (lane == firstlane) { out[b] = (float)cand; out[BB + b] = logf(pv); }
        }
    }
}

// ---------------- kernel 5: aux ----------------
__global__ void k_aux(float* __restrict__ out) {
    if (threadIdx.x == 0 && blockIdx.x == 0) {
        float s = 0.f;
#pragma unroll
        for (int r = 0; r < RR; r++) s += g_sumP[r] * g_sumM[r];
        out[2 * BB] = (float)RR * 0.05f * s / ((float)BB * (float)BB);
    }
}

// ---------------- launch ----------------
extern "C" void kernel_launch(void* const* d_in, const int* in_sizes, int n_in,
                              void* d_out, int out_size) {
    const float* x   = (const float*)d_in[0];
    const float* re  = (const float*)d_in[1];
    const float* rnd = (const float*)d_in[2];
    const float* gw  = (const float*)d_in[3];
    const float* gb  = (const float*)d_in[4];
    const float* Uw  = (const float*)d_in[5];
    const float* Ub  = (const float*)d_in[6];
    const float* Vw  = (const float*)d_in[7];
    const float* Vb  = (const float*)d_in[8];
    float* out = (float*)d_out;

    const int dyn_bytes = (16 * EE + 2 * HH * DPAD) * sizeof(float);  // ~74.8KB
    cudaFuncSetAttribute(k_main, cudaFuncAttributeMaxDynamicSharedMemorySize, dyn_bytes);

    k_init<<<1, 128>>>();
    k_gate<<<BB / 8, 256>>>(x, gw, gb);
    k_sched<<<1, 256>>>();
    k_uv<<<GRID_UV, 256>>>(x, re, Uw, Ub, Vw, Vb);
    k_main<<<GRID_MAIN, 256, dyn_bytes>>>(rnd, out);
    k_aux<<<1, 32>>>(out);
}

// round 7
// speedup vs baseline: 1.0968x; 1.0968x over previous
#include <cuda_runtime.h>
#include <math.h>

#define BB 8192
#define DD 384
#define EE 1024
#define RR 8
#define HH 64
#define DPAD 18
#define GRID_UV 444        // 3 * 148: column-major SM-affine tile slots
#define GRID_MAIN 640
#define DC 64              // d-chunk for k_uv
#define XSTR 68
#define NCH (DD / DC)      // 6 chunks

typedef unsigned long long ull;

// ---------------- device scratch ----------------
__device__ float g_evt[RR * HH * EE];
__device__ float g_xu[BB * 2 * HH];
__device__ float g_gw[BB * 2];
__device__ int   g_cnt[RR];
__device__ int   g_list[RR * BB];
__device__ int   g_pcnt[64];
__device__ int   g_plist[64 * BB];
__device__ int   g_uvtile[GRID_UV];
__device__ int   g_ptile[GRID_MAIN];
__device__ float g_sumP[RR];
__device__ float g_sumM[RR];

// ---------------- f32x2 helpers ----------------
__device__ __forceinline__ ull pk2(float a, float b) {
    ull r; asm("mov.b64 %0, {%1,%2};" : "=l"(r) : "f"(a), "f"(b)); return r;
}
__device__ __forceinline__ void upk2(ull v, float& lo, float& hi) {
    asm("mov.b64 {%0,%1}, %2;" : "=f"(lo), "=f"(hi) : "l"(v));
}
__device__ __forceinline__ ull fma2(ull a, ull b, ull c) {
    ull d; asm("fma.rn.f32x2 %0, %1, %2, %3;" : "=l"(d) : "l"(a), "l"(b), "l"(c)); return d;
}

// ---------------- kernel 0: init ----------------
__global__ void k_init() {
    int t = threadIdx.x;
    if (t < RR) { g_cnt[t] = 0; g_sumP[t] = 0.f; g_sumM[t] = 0.f; }
    if (t < 64) g_pcnt[t] = 0;
}

// ---------------- kernel 1: gate ----------------
__global__ void __launch_bounds__(256) k_gate(const float* __restrict__ x,
                                              const float* __restrict__ gw,
                                              const float* __restrict__ gb) {
    __shared__ float sP[RR], sM[RR];
    int tid = threadIdx.x;
    if (tid < RR) { sP[tid] = 0.f; sM[tid] = 0.f; }
    __syncthreads();

    int warp = tid >> 5, lane = tid & 31;
    int b = blockIdx.x * 8 + warp;

    float acc[RR];
#pragma unroll
    for (int r = 0; r < RR; r++) acc[r] = 0.f;
    const float* xr = x + b * DD;
    for (int d = lane; d < DD; d += 32) {
        float xv = xr[d];
        const float4* g4 = (const float4*)(gw + d * RR);
        float4 a = g4[0], c = g4[1];
        acc[0] += xv * a.x; acc[1] += xv * a.y; acc[2] += xv * a.z; acc[3] += xv * a.w;
        acc[4] += xv * c.x; acc[5] += xv * c.y; acc[6] += xv * c.z; acc[7] += xv * c.w;
    }
#pragma unroll
    for (int r = 0; r < RR; r++)
#pragma unroll
        for (int o = 16; o; o >>= 1) acc[r] += __shfl_xor_sync(0xffffffffu, acc[r], o);

    if (lane == 0) {
        float lg[RR];
#pragma unroll
        for (int r = 0; r < RR; r++) lg[r] = acc[r] + gb[r];
        int i0 = 0; float v0 = lg[0];
#pragma unroll
        for (int r = 1; r < RR; r++) if (lg[r] > v0) { v0 = lg[r]; i0 = r; }
        int i1 = -1; float v1 = -3.0e38f;
#pragma unroll
        for (int r = 0; r < RR; r++) if (r != i0 && lg[r] > v1) { v1 = lg[r]; i1 = r; }

        float s = 0.f, pr[RR];
#pragma unroll
        for (int r = 0; r < RR; r++) { pr[r] = expf(lg[r] - v0); s += pr[r]; }
        float inv = 1.f / s;
#pragma unroll
        for (int r = 0; r < RR; r++) atomicAdd(&sP[r], pr[r] * inv);
        atomicAdd(&sM[i0], 1.f);
        atomicAdd(&sM[i1], 1.f);

        float e1 = expf(v1 - v0);
        float den = 1.f / (1.f + e1);
        g_gw[b * 2 + 0] = den;
        g_gw[b * 2 + 1] = e1 * den;

        int p0 = atomicAdd(&g_cnt[i0], 1); g_list[i0 * BB + p0] = b * 2 + 0;
        int p1 = atomicAdd(&g_cnt[i1], 1); g_list[i1 * BB + p1] = b * 2 + 1;

        int pid = i0 * 8 + i1;
        int pp = atomicAdd(&g_pcnt[pid], 1); g_plist[pid * BB + pp] = b;
    }
    __syncthreads();
    if (tid < RR) { atomicAdd(&g_sumP[tid], sP[tid]); atomicAdd(&g_sumM[tid], sM[tid]); }
}

// ---------------- kernel 2: scheduler (SM-affine column-major tile scatter) ----------------
__global__ void k_sched() {
    __shared__ int list[GRID_UV];
    __shared__ int roff[RR], poff[64];
    int tid = threadIdx.x;
    for (int i = tid; i < GRID_UV; i += 256) list[i] = -1;
    for (int i = tid; i < GRID_MAIN; i += 256) g_ptile[i] = -1;
    __syncthreads();
    if (tid == 0) {
        int o = 128;   // xu classes start after 128 ev tiles
        for (int r = 0; r < RR; r++) { roff[r] = o; o += (g_cnt[r] + 63) >> 6; }
        o = 0;
        for (int p = 0; p < 64; p++) { poff[p] = o; o += (g_pcnt[p] + 15) >> 4; }
    }
    __syncthreads();
    if (tid < 128) list[tid] = ((tid >> 4) << 24) | (tid & 15);   // ev: class (0, r)
    if (tid >= 128 && tid < 128 + RR) {
        int r = tid - 128;
        int n = (g_cnt[r] + 63) >> 6;
        for (int i = 0; i < n; i++) list[roff[r] + i] = (1 << 28) | (r << 24) | i;
    }
    if (tid >= 192 && tid < 256) {
        int p = tid - 192;
        int n = (g_pcnt[p] + 15) >> 4;
        for (int i = 0; i < n; i++) g_ptile[poff[p] + i] = (p << 16) | i;
    }
    __syncthreads();
    // scatter: bid = k*148 + sm receives list[sm*3 + k] -> same-SM bids share class
    for (int bid = tid; bid < GRID_UV; bid += 256) {
        int k = bid / 148, sm = bid - k * 148;
        g_uvtile[bid] = list[sm * 3 + k];
    }
}

// ---------------- kernel 3: unified ev/xu GEMM (128 thr, 64x64, pipelined) ----------------
__global__ void __launch_bounds__(128) k_uv(const float* __restrict__ x,
                                            const float* __restrict__ re,
                                            const float* __restrict__ Uw,
                                            const float* __restrict__ Ub,
                                            const float* __restrict__ Vw,
                                            const float* __restrict__ Vb) {
    __shared__ float xT[2][DC * XSTR];   // double-buffered transposed x  (34.8 KB)
    __shared__ int   s_code[64];

    int info = g_uvtile[blockIdx.x];
    if (info < 0) return;
    int type = (info >> 28) & 1;
    int r    = (info >> 24) & 15;
    int tile = info & 0xffffff;
    int tid = threadIdx.x;

    const float* W    = (type == 0) ? (Vw + r * DD * HH) : (Uw + r * DD * HH);
    const float* bias = (type == 0) ? (Vb + r * HH)      : (Ub + r * HH);
    const float4* W4  = (const float4*)W;   // [d][HH/4]

    if (tid < 64) {
        if (type == 0) s_code[tid] = tile * 64 + tid;
        else {
            int cnt = g_cnt[r], base = tile * 64;
            s_code[tid] = (base + tid < cnt) ? g_list[r * BB + base + tid] : -1;
        }
    }
    __syncthreads();

    int w = tid >> 5, l = tid & 31;
    int hq = l & 15, rg = l >> 4;
    int h0 = hq * 4;
    int wrow = w * 16 + rg * 8;          // 8 rows (4 f32x2 pairs) per lane

    int srow = tid & 63, shalf = tid >> 6;   // stage row srow, d-half shalf (32 d)
    const float* src;
    {
        int c = s_code[srow];
        if (type == 0) src = re + (long)c * DD;
        else           src = (c >= 0) ? (x + (long)(c >> 1) * DD) : (const float*)0;
    }

    ull acc[4][4];
#pragma unroll
    for (int a = 0; a < 4; a++)
#pragma unroll
        for (int b = 0; b < 4; b++) acc[a][b] = 0ULL;

    // ---- prologue: stage chunk 0 ----
    {
        float4 sv[8];
#pragma unroll
        for (int i = 0; i < 8; i++)
            sv[i] = src ? __ldcs((const float4*)(src + shalf * 32 + i * 4))
                        : make_float4(0.f, 0.f, 0.f, 0.f);
#pragma unroll
        for (int i = 0; i < 8; i++) {
            int d = shalf * 32 + i * 4;
            xT[0][(d + 0) * XSTR + srow] = sv[i].x; xT[0][(d + 1) * XSTR + srow] = sv[i].y;
            xT[0][(d + 2) * XSTR + srow] = sv[i].z; xT[0][(d + 3) * XSTR + srow] = sv[i].w;
        }
    }
    __syncthreads();

    for (int c = 0; c < NCH; c++) {
        int cur = c & 1;
        // issue next chunk's LDGs up-front (streaming, evict-first: keep W in L1)
        float4 nv[8];
        bool more = (c + 1 < NCH);
        if (more && src) {
            const float* sp = src + (c + 1) * DC + shalf * 32;
#pragma unroll
            for (int i = 0; i < 8; i++) nv[i] = __ldcs((const float4*)(sp + i * 4));
        }

        const float* xb = xT[cur];
        // W prefetch pipeline, depth 4
        float4 wq[4];
#pragma unroll
        for (int i = 0; i < 4; i++) wq[i] = W4[(c * DC + i) * (HH / 4) + hq];

#pragma unroll
        for (int d0 = 0; d0 < DC; d0 += 4) {
            float4 wn[4];
            if (d0 + 4 < DC) {
#pragma unroll
                for (int i = 0; i < 4; i++) wn[i] = W4[(c * DC + d0 + 4 + i) * (HH / 4) + hq];
            }
#pragma unroll
            for (int dd = 0; dd < 4; dd++) {
                float4 wv = wq[dd];
                ull b0 = pk2(wv.x, wv.x), b1 = pk2(wv.y, wv.y);
                ull b2 = pk2(wv.z, wv.z), b3 = pk2(wv.w, wv.w);
                const ull* xp = (const ull*)&xb[(d0 + dd) * XSTR + wrow];
                ull x0 = xp[0], x1 = xp[1], x2 = xp[2], x3 = xp[3];
                acc[0][0] = fma2(x0, b0, acc[0][0]); acc[0][1] = fma2(x0, b1, acc[0][1]);
                acc[0][2] = fma2(x0, b2, acc[0][2]); acc[0][3] = fma2(x0, b3, acc[0][3]);
                acc[1][0] = fma2(x1, b0, acc[1][0]); acc[1][1] = fma2(x1, b1, acc[1][1]);
                acc[1][2] = fma2(x1, b2, acc[1][2]); acc[1][3] = fma2(x1, b3, acc[1][3]);
                acc[2][0] = fma2(x2, b0, acc[2][0]); acc[2][1] = fma2(x2, b1, acc[2][1]);
                acc[2][2] = fma2(x2, b2, acc[2][2]); acc[2][3] = fma2(x2, b3, acc[2][3]);
                acc[3][0] = fma2(x3, b0, acc[3][0]); acc[3][1] = fma2(x3, b1, acc[3][1]);
                acc[3][2] = fma2(x3, b2, acc[3][2]); acc[3][3] = fma2(x3, b3, acc[3][3]);
            }
            if (d0 + 4 < DC) {
#pragma unroll
                for (int i = 0; i < 4; i++) wq[i] = wn[i];
            }
        }

        // store staged data for next chunk
        if (more) {
            float* nb = xT[cur ^ 1];
            if (src) {
#pragma unroll
                for (int i = 0; i < 8; i++) {
                    int d = shalf * 32 + i * 4;
                    nb[(d + 0) * XSTR + srow] = nv[i].x; nb[(d + 1) * XSTR + srow] = nv[i].y;
                    nb[(d + 2) * XSTR + srow] = nv[i].z; nb[(d + 3) * XSTR + srow] = nv[i].w;
                }
            } else {
#pragma unroll
                for (int i = 0; i < 8; i++) {
                    int d = shalf * 32 + i * 4;
                    nb[(d + 0) * XSTR + srow] = 0.f; nb[(d + 1) * XSTR + srow] = 0.f;
                    nb[(d + 2) * XSTR + srow] = 0.f; nb[(d + 3) * XSTR + srow] = 0.f;
                }
            }
        }
        __syncthreads();
    }

    // ---- epilogue: bias, per-row l2 norm (reduce over 16 h-lanes), store ----
    float bl[4];
#pragma unroll
    for (int k = 0; k < 4; k++) bl[k] = bias[h0 + k];

#pragma unroll
    for (int rp = 0; rp < 4; rp++) {
        float vlo[4], vhi[4];
        float slo = 0.f, shi = 0.f;
#pragma unroll
        for (int k = 0; k < 4; k++) {
            float lo, hi;
            upk2(acc[rp][k], lo, hi);
            lo += bl[k]; hi += bl[k];
            vlo[k] = lo; vhi[k] = hi;
            slo += lo * lo; shi += hi * hi;
        }
#pragma unroll
        for (int o = 1; o <= 8; o <<= 1) {
            slo += __shfl_xor_sync(0xffffffffu, slo, o);
            shi += __shfl_xor_sync(0xffffffffu, shi, o);
        }
        float rnlo = 1.f / fmaxf(sqrtf(slo), 1e-12f);
        float rnhi = 1.f / fmaxf(sqrtf(shi), 1e-12f);

        int row0 = wrow + 2 * rp;
        if (type == 1) {
            int c0 = s_code[row0], c1 = s_code[row0 + 1];
            if (c0 >= 0) {
                float4 o0 = make_float4(vlo[0] * rnlo, vlo[1] * rnlo, vlo[2] * rnlo, vlo[3] * rnlo);
                *(float4*)(g_xu + c0 * HH + h0) = o0;
            }
            if (c1 >= 0) {
                float4 o1 = make_float4(vhi[0] * rnhi, vhi[1] * rnhi, vhi[2] * rnhi, vhi[3] * rnhi);
                *(float4*)(g_xu + c1 * HH + h0) = o1;
            }
        } else {
#pragma unroll
            for (int k = 0; k < 4; k++) {
                xT[0][(h0 + k) * XSTR + row0]     = vlo[k] * rnlo;   // outT[h][row]
                xT[0][(h0 + k) * XSTR + row0 + 1] = vhi[k] * rnhi;
            }
        }
    }
    if (type == 0) {
        __syncthreads();
        int h = tid >> 1, half = tid & 1;
        int ebase = tile * 64;
        float* dst = g_evt + (r * HH + h) * EE + ebase + half * 32;
        const float* s = &xT[0][h * XSTR + half * 32];
#pragma unroll
        for (int i = 0; i < 8; i++) {
            float4 o = make_float4(s[i * 4 + 0], s[i * 4 + 1], s[i * 4 + 2], s[i * 4 + 3]);
            *(float4*)(dst + i * 4) = o;
        }
    }
}

// ---------------- kernel 4: pair-grouped scores + softmax + combine + sample ----------------
__global__ void __launch_bounds__(256, 2) k_main(const float* __restrict__ rnd,
                                                 float* __restrict__ out) {
    extern __shared__ float dyn[];
    float* p_s = dyn;                            // [16][1024]  64KB
    float* xu_s = dyn + 16 * EE;                 // [2][64][18] 9.2KB
    __shared__ int   s_b[16];
    __shared__ float s_w[2][16];
    __shared__ float red[8][16];
    __shared__ float rowstat[16];
    __shared__ float s_scale[16];

    int info = g_ptile[blockIdx.x];
    if (info < 0) return;
    int pid = info >> 16, base = (info & 0xffff) * 16;
    int r0 = pid >> 3, r1 = pid & 7;
    int cnt = g_pcnt[pid];
    int nt = min(16, cnt - base);
    int tid = threadIdx.x;

    if (tid < 16) {
        int b = (tid < nt) ? g_plist[pid * BB + base + tid] : -1;
        s_b[tid] = b;
        s_w[0][tid] = (b >= 0) ? g_gw[b * 2 + 0] : 0.f;
        s_w[1][tid] = (b >= 0) ? g_gw[b * 2 + 1] : 0.f;
    }
    __syncthreads();
    {
        int s = tid >> 7, c = (tid >> 3) & 15, h0 = (tid & 7) * 8;
        int b = s_b[c];
        float* dst = xu_s + s * (HH * DPAD);
        if (b >= 0) {
            const float4* src = (const float4*)(g_xu + (b * 2 + s) * HH + h0);
            float4 v0 = src[0], v1 = src[1];
            dst[(h0 + 0) * DPAD + c] = v0.x; dst[(h0 + 1) * DPAD + c] = v0.y;
            dst[(h0 + 2) * DPAD + c] = v0.z; dst[(h0 + 3) * DPAD + c] = v0.w;
            dst[(h0 + 4) * DPAD + c] = v1.x; dst[(h0 + 5) * DPAD + c] = v1.y;
            dst[(h0 + 6) * DPAD + c] = v1.z; dst[(h0 + 7) * DPAD + c] = v1.w;
        } else {
#pragma unroll
            for (int j = 0; j < 8; j++) dst[(h0 + j) * DPAD + c] = 0.f;
        }
    }
    __syncthreads();

    int e0 = tid * 4;
    int lane = tid & 31, w = tid >> 5;

    for (int ph = 0; ph < 2; ph++) {
        int r = ph ? r1 : r0;
        ull acc2[8][4];
#pragma unroll
        for (int tp = 0; tp < 8; tp++)
#pragma unroll
            for (int j = 0; j < 4; j++) acc2[tp][j] = 0ULL;

        const float* evr = g_evt + r * HH * EE;
        const float* xub = xu_s + ph * (HH * DPAD);
#pragma unroll 4
        for (int h = 0; h < HH; h++) {
            float4 ev4 = *(const float4*)(evr + h * EE + e0);
            ull bx = pk2(ev4.x, ev4.x);
            ull by = pk2(ev4.y, ev4.y);
            ull bz = pk2(ev4.z, ev4.z);
            ull bw = pk2(ev4.w, ev4.w);
            const ull* xp = (const ull*)(xub + h * DPAD);
#pragma unroll
            for (int tp = 0; tp < 8; tp++) {
                ull xs2 = xp[tp];
                acc2[tp][0] = fma2(xs2, bx, acc2[tp][0]);
                acc2[tp][1] = fma2(xs2, by, acc2[tp][1]);
                acc2[tp][2] = fma2(xs2, bz, acc2[tp][2]);
                acc2[tp][3] = fma2(xs2, bw, acc2[tp][3]);
            }
        }

        {
            float lmax[16];
#pragma unroll
            for (int t = 0; t < 16; t++) lmax[t] = -3.0e38f;
#pragma unroll
            for (int tp = 0; tp < 8; tp++)
#pragma unroll
                for (int j = 0; j < 4; j++) {
                    float lo, hi;
                    upk2(acc2[tp][j], lo, hi);
                    lmax[2 * tp]     = fmaxf(lmax[2 * tp], lo);
                    lmax[2 * tp + 1] = fmaxf(lmax[2 * tp + 1], hi);
                }
#pragma unroll
            for (int t = 0; t < 16; t++)
#pragma unroll
                for (int o = 16; o; o >>= 1)
                    lmax[t] = fmaxf(lmax[t], __shfl_xor_sync(0xffffffffu, lmax[t], o));
            if (lane == 0)
#pragma unroll
                for (int t = 0; t < 16; t++) red[w][t] = lmax[t];
        }
        __syncthreads();
        if (tid < 16) {
            float m = red[0][tid];
#pragma unroll
            for (int ww = 1; ww < 8; ww++) m = fmaxf(m, red[ww][tid]);
            rowstat[tid] = m;
        }
        __syncthreads();

        {
            float lsum[16];
#pragma unroll
            for (int t = 0; t < 16; t++) lsum[t] = 0.f;
#pragma unroll
            for (int tp = 0; tp < 8; tp++) {
                float m0 = rowstat[2 * tp], m1 = rowstat[2 * tp + 1];
#pragma unroll
                for (int j = 0; j < 4; j++) {
                    float lo, hi;
                    upk2(acc2[tp][j], lo, hi);
                    float elo = __expf(lo - m0);
                    float ehi = __expf(hi - m1);
                    lsum[2 * tp]     += elo;
                    lsum[2 * tp + 1] += ehi;
                    acc2[tp][j] = pk2(elo, ehi);
                }
            }
#pragma unroll
            for (int t = 0; t < 16; t++)
#pragma unroll
                for (int o = 16; o; o >>= 1)
                    lsum[t] += __shfl_xor_sync(0xffffffffu, lsum[t], o);
            if (lane == 0)
#pragma unroll
                for (int t = 0; t < 16; t++) red[w][t] = lsum[t];
        }
        __syncthreads();
        if (tid < 16) {
            float s = 0.f;
#pragma unroll
            for (int ww = 0; ww < 8; ww++) s += red[ww][tid];
            s_scale[tid] = s_w[ph][tid] / s;
        }
        __syncthreads();

#pragma unroll
        for (int tp = 0; tp < 8; tp++) {
            int t0 = 2 * tp, t1 = 2 * tp + 1;
            float sc0 = s_scale[t0], sc1 = s_scale[t1];
            float4 olo, ohi;
            float lo, hi;
            upk2(acc2[tp][0], lo, hi); olo.x = lo * sc0; ohi.x = hi * sc1;
            upk2(acc2[tp][1], lo, hi); olo.y = lo * sc0; ohi.y = hi * sc1;
            upk2(acc2[tp][2], lo, hi); olo.z = lo * sc0; ohi.z = hi * sc1;
            upk2(acc2[tp][3], lo, hi); olo.w = lo * sc0; ohi.w = hi * sc1;
            float4* d0 = (float4*)(p_s + t0 * EE + e0);
            float4* d1 = (float4*)(p_s + t1 * EE + e0);
            if (ph == 0) {
                *d0 = olo; *d1 = ohi;
            } else {
                float4 a = *d0, c = *d1;
                a.x += olo.x; a.y += olo.y; a.z += olo.z; a.w += olo.w;
                c.x += ohi.x; c.y += ohi.y; c.z += ohi.z; c.w += ohi.w;
                *d0 = a; *d1 = c;
            }
        }
        __syncthreads();
    }

#pragma unroll
    for (int k = 0; k < 2; k++) {
        int t = w * 2 + k;
        int b = s_b[t];
        if (b < 0) continue;
        float rv = rnd[b];
        int ebase2 = lane * 32;
        float v[32];
        const float4* pr = (const float4*)(p_s + t * EE + ebase2);
#pragma unroll
        for (int q = 0; q < 8; q++) {
            float4 f = pr[q];
            v[q * 4 + 0] = f.x; v[q * 4 + 1] = f.y; v[q * 4 + 2] = f.z; v[q * 4 + 3] = f.w;
        }
        float lsum = 0.f;
#pragma unroll
        for (int i = 0; i < 32; i++) lsum += v[i];
        float sc = lsum;
#pragma unroll
        for (int o = 1; o < 32; o <<= 1) {
            float u = __shfl_up_sync(0xffffffffu, sc, o);
            if (lane >= o) sc += u;
        }
        float run = sc - lsum;
        int cand = 0x7fffffff;
        float pv = 0.f;
#pragma unroll
        for (int i = 0; i < 32; i++) {
            run += v[i];
            if (cand == 0x7fffffff && run > rv) { cand = ebase2 + i; pv = v[i]; }
        }
        unsigned mask = __ballot_sync(0xffffffffu, cand != 0x7fffffff);
        if (mask == 0) {
            if (lane == 0) { out[b] = 0.f; out[BB + b] = logf(v[0]); }
        } else {
            int firstlane = __ffs(mask) - 1;
            if (lane == firstlane) { out[b] = (float)cand; out[BB + b] = logf(pv); }
        }
    }
}

// ---------------- kernel 5: aux ----------------
__global__ void k_aux(float* __restrict__ out) {
    if (threadIdx.x == 0 && blockIdx.x == 0) {
        float s = 0.f;
#pragma unroll
        for (int r = 0; r < RR; r++) s += g_sumP[r] * g_sumM[r];
        out[2 * BB] = (float)RR * 0.05f * s / ((float)BB * (float)BB);
    }
}

// ---------------- launch ----------------
extern "C" void kernel_launch(void* const* d_in, const int* in_sizes, int n_in,
                              void* d_out, int out_size) {
    const float* x   = (const float*)d_in[0];
    const float* re  = (const float*)d_in[1];
    const float* rnd = (const float*)d_in[2];
    const float* gw  = (const float*)d_in[3];
    const float* gb  = (const float*)d_in[4];
    const float* Uw  = (const float*)d_in[5];
    const float* Ub  = (const float*)d_in[6];
    const float* Vw  = (const float*)d_in[7];
    const float* Vb  = (const float*)d_in[8];
    float* out = (float*)d_out;

    const int dyn_bytes = (16 * EE + 2 * HH * DPAD) * sizeof(float);  // ~74.8KB
    cudaFuncSetAttribute(k_main, cudaFuncAttributeMaxDynamicSharedMemorySize, dyn_bytes);

    k_init<<<1, 128>>>();
    k_gate<<<BB / 8, 256>>>(x, gw, gb);
    k_sched<<<1, 256>>>();
    k_uv<<<GRID_UV, 128>>>(x, re, Uw, Ub, Vw, Vb);
    k_main<<<GRID_MAIN, 256, dyn_bytes>>>(rnd, out);
    k_aux<<<1, 32>>>(out);
}